// round 3
// baseline (speedup 1.0000x reference)
#include <cuda_runtime.h>
#include <cuda_fp16.h>
#include <cuda.h>
#include <cstdint>

// ============================================================================
// out[8192,4096] = densify(COO) @ W^T + bias
// fp16 densify + TMA/mbarrier pipeline + mma.sync (no tcgen05: harness PTX
// target is sm_103 without the 'a' feature suffix).
// ============================================================================

static constexpr int MDIM = 8192;
static constexpr int NDIM = 4096;
static constexpr int KDIM = 4096;

static constexpr int BM = 128;
static constexpr int BN = 128;
static constexpr int BK = 64;              // 64 f16 = 128B row -> SW128 native
static constexpr int STAGES = 4;
static constexpr int KITERS = KDIM / BK;   // 64

static constexpr int NTHREADS = 288;       // 8 compute warps + 1 producer warp

// Device-global scratch (no allocation allowed)
__device__ __half g_A[(size_t)MDIM * KDIM];   // 64 MB densified fp16 A
__device__ __half g_W[(size_t)NDIM * KDIM];   // 32 MB fp16 weight

// ----- SMEM layout -----
static constexpr int OFF_FULL  = 0;                      // 4 mbarriers
static constexpr int OFF_EMPTY = 32;                     // 4 mbarriers
static constexpr int OFF_A     = 1024;
static constexpr int STAGE_A   = BM * BK * 2;            // 16384
static constexpr int OFF_B     = OFF_A + STAGES * STAGE_A;   // 66560
static constexpr int STAGE_B   = BN * BK * 2;            // 16384
static constexpr int SMEM_TOTAL = OFF_B + STAGES * STAGE_B;  // 132096

#define DEV_INLINE __device__ __forceinline__

DEV_INLINE uint32_t smem_u32(const void* p) {
    uint32_t a;
    asm("{ .reg .u64 t; cvta.to.shared.u64 t, %1; cvt.u32.u64 %0, t; }" : "=r"(a) : "l"(p));
    return a;
}

DEV_INLINE void mbar_init(uint32_t mbar, uint32_t count) {
    asm volatile("mbarrier.init.shared.b64 [%0], %1;" :: "r"(mbar), "r"(count) : "memory");
}

DEV_INLINE void mbar_expect_tx(uint32_t mbar, uint32_t bytes) {
    asm volatile("mbarrier.arrive.expect_tx.shared.b64 _, [%0], %1;"
                 :: "r"(mbar), "r"(bytes) : "memory");
}

DEV_INLINE void mbar_arrive(uint32_t mbar) {
    asm volatile("mbarrier.arrive.shared.b64 _, [%0];" :: "r"(mbar) : "memory");
}

DEV_INLINE void mbar_wait(uint32_t mbar, uint32_t parity) {
    asm volatile(
        "{\n\t.reg .pred P;\n\t"
        "W_%=:\n\t"
        "mbarrier.try_wait.parity.acquire.cta.shared::cta.b64 P, [%0], %1, 0x989680;\n\t"
        "@P bra.uni D_%=;\n\t"
        "bra.uni W_%=;\n\t"
        "D_%=:\n\t}"
        :: "r"(mbar), "r"(parity) : "memory");
}

DEV_INLINE void mbar_wait_relaxed(uint32_t mbar, uint32_t parity) {
    asm volatile(
        "{\n\t.reg .pred P;\n\t"
        "W_%=:\n\t"
        "mbarrier.try_wait.parity.relaxed.cta.shared::cta.b64 P, [%0], %1, 0x989680;\n\t"
        "@P bra.uni D_%=;\n\t"
        "bra.uni W_%=;\n\t"
        "D_%=:\n\t}"
        :: "r"(mbar), "r"(parity) : "memory");
}

DEV_INLINE void tma_load_2d(uint32_t dst, const CUtensorMap* map, int x, int y, uint32_t mbar) {
    asm volatile(
        "cp.async.bulk.tensor.2d.shared::cta.global.tile.mbarrier::complete_tx::bytes "
        "[%0], [%1, {%2, %3}], [%4];"
        :: "r"(dst), "l"(map), "r"(x), "r"(y), "r"(mbar) : "memory");
}

DEV_INLINE void ldsm_x4(uint32_t& r0, uint32_t& r1, uint32_t& r2, uint32_t& r3, uint32_t addr) {
    asm volatile("ldmatrix.sync.aligned.m8n8.x4.shared.b16 {%0, %1, %2, %3}, [%4];"
                 : "=r"(r0), "=r"(r1), "=r"(r2), "=r"(r3) : "r"(addr));
}

DEV_INLINE void mma_16816(float& d0, float& d1, float& d2, float& d3,
                          uint32_t a0, uint32_t a1, uint32_t a2, uint32_t a3,
                          uint32_t b0, uint32_t b1) {
    asm volatile(
        "mma.sync.aligned.m16n8k16.row.col.f32.f16.f16.f32 "
        "{%0, %1, %2, %3}, {%4, %5, %6, %7}, {%8, %9}, {%0, %1, %2, %3};"
        : "+f"(d0), "+f"(d1), "+f"(d2), "+f"(d3)
        : "r"(a0), "r"(a1), "r"(a2), "r"(a3), "r"(b0), "r"(b1));
}

// ============================================================================
// Prep kernels
// ============================================================================

__global__ void zero_a_kernel() {
    size_t n16 = (size_t)MDIM * KDIM * 2 / 16;
    uint4* p = reinterpret_cast<uint4*>(g_A);
    uint4 z = make_uint4(0, 0, 0, 0);
    for (size_t i = (size_t)blockIdx.x * blockDim.x + threadIdx.x; i < n16;
         i += (size_t)gridDim.x * blockDim.x)
        p[i] = z;
}

__global__ void convert_w_kernel(const float* __restrict__ w) {
    size_t n2 = (size_t)NDIM * KDIM / 2;
    const float2* src = reinterpret_cast<const float2*>(w);
    __half2* dst = reinterpret_cast<__half2*>(g_W);
    for (size_t i = (size_t)blockIdx.x * blockDim.x + threadIdx.x; i < n2;
         i += (size_t)gridDim.x * blockDim.x) {
        float2 f = src[i];
        dst[i] = __floats2half2_rn(f.x, f.y);
    }
}

__global__ void scatter_kernel(const float* __restrict__ vals,
                               const int* __restrict__ rows,
                               const int* __restrict__ cols, int nnz) {
    int i = blockIdx.x * blockDim.x + threadIdx.x;
    if (i < nnz) {
        size_t idx = (size_t)rows[i] * KDIM + cols[i];
        atomicAdd(&g_A[idx], __float2half_rn(vals[i]));
    }
}

// ============================================================================
// GEMM kernel: TMA producer warp + 8 mma.sync compute warps
// Warp grid 2(m) x 4(n): warp tile 64x32. 16 m16n8k16 mma per k16 step.
// ============================================================================

__global__ void __launch_bounds__(NTHREADS, 1) gemm_f16_kernel(
    const __grid_constant__ CUtensorMap tmA,
    const __grid_constant__ CUtensorMap tmB,
    const float* __restrict__ bias,
    float* __restrict__ out)
{
    extern __shared__ char smem[];
    uint32_t sb = smem_u32(smem);
    int tid = threadIdx.x;
    int wid = tid >> 5;
    int lid = tid & 31;
    int m0 = blockIdx.y * BM;
    int n0 = blockIdx.x * BN;

    if (tid == 0) {
        for (int s = 0; s < STAGES; s++) {
            mbar_init(sb + OFF_FULL + s * 8, 1);    // producer expect_tx arrives
            mbar_init(sb + OFF_EMPTY + s * 8, 8);   // one arrive per compute warp
        }
    }
    __syncthreads();

    if (wid == 8) {
        // ---------------- TMA producer warp ----------------
        if (lid == 0) {
            int stage = 0, phase = 1;  // fresh empty barriers: parity-1 wait passes
            for (int it = 0; it < KITERS; ++it) {
                mbar_wait_relaxed(sb + OFF_EMPTY + stage * 8, phase);
                mbar_expect_tx(sb + OFF_FULL + stage * 8, STAGE_A + STAGE_B);
                tma_load_2d(sb + OFF_A + stage * STAGE_A, &tmA, it * BK, m0,
                            sb + OFF_FULL + stage * 8);
                tma_load_2d(sb + OFF_B + stage * STAGE_B, &tmB, it * BK, n0,
                            sb + OFF_FULL + stage * 8);
                if (++stage == STAGES) { stage = 0; phase ^= 1; }
            }
        }
        return;
    }

    // ---------------- compute warps ----------------
    int warp_m = wid >> 2;        // 0..1 -> row offset warp_m*64
    int warp_n = wid & 3;         // 0..3 -> col offset warp_n*32

    // ldmatrix per-lane address components (SW128: swz(r*128+u*16) = r*128 + ((u^(r&7))*16))
    // A x4 frag (m16 x k16): mat = lid/8; m_in = (mat%2)*8 + lid%8; khalf = mat/2
    int a_row0 = warp_m * 64 + ((lid >> 3) & 1) * 8 + (lid & 7);
    int a_kh   = lid >> 4;
    int a_x7   = lid & 7;
    // B x4 frag (n16 x k16): mat = lid/8; n_in = (mat/2)*8 + lid%8; khalf = mat%2
    int b_row0 = warp_n * 32 + (lid >> 4) * 8 + (lid & 7);
    int b_kh   = (lid >> 3) & 1;
    int b_x7   = lid & 7;

    float c[4][4][4];   // [im][n8][reg]
    #pragma unroll
    for (int i = 0; i < 4; i++)
        #pragma unroll
        for (int j = 0; j < 4; j++)
            #pragma unroll
            for (int k = 0; k < 4; k++)
                c[i][j][k] = 0.0f;

    int stage = 0, phase = 0;
    for (int it = 0; it < KITERS; ++it) {
        mbar_wait(sb + OFF_FULL + stage * 8, phase);
        uint32_t aBase = sb + OFF_A + stage * STAGE_A;
        uint32_t bBase = sb + OFF_B + stage * STAGE_B;

        #pragma unroll
        for (int s4 = 0; s4 < 4; s4++) {   // 4 x k16 per BK=64
            uint32_t a[4][4];
            #pragma unroll
            for (int im = 0; im < 4; im++) {
                int row = a_row0 + im * 16;
                uint32_t addr = aBase + row * 128 + (((s4 * 2 + a_kh) ^ a_x7) << 4);
                ldsm_x4(a[im][0], a[im][1], a[im][2], a[im][3], addr);
            }
            uint32_t b[2][4];
            #pragma unroll
            for (int jn = 0; jn < 2; jn++) {
                int row = b_row0 + jn * 16;
                uint32_t addr = bBase + row * 128 + (((s4 * 2 + b_kh) ^ b_x7) << 4);
                ldsm_x4(b[jn][0], b[jn][1], b[jn][2], b[jn][3], addr);
            }
            #pragma unroll
            for (int im = 0; im < 4; im++)
                #pragma unroll
                for (int in_ = 0; in_ < 4; in_++) {
                    int j = in_ >> 1, p = (in_ & 1) * 2;
                    mma_16816(c[im][in_][0], c[im][in_][1], c[im][in_][2], c[im][in_][3],
                              a[im][0], a[im][1], a[im][2], a[im][3],
                              b[j][p], b[j][p + 1]);
                }
        }

        if (lid == 0) mbar_arrive(sb + OFF_EMPTY + stage * 8);
        if (++stage == STAGES) { stage = 0; phase ^= 1; }
    }

    // ---------------- epilogue: c + bias -> out ----------------
    int col_base = n0 + warp_n * 32 + (lid & 3) * 2;
    int row_base = m0 + warp_m * 64 + (lid >> 2);
    #pragma unroll
    for (int in_ = 0; in_ < 4; in_++) {
        int col = col_base + in_ * 8;
        float2 b2 = *reinterpret_cast<const float2*>(bias + col);
        #pragma unroll
        for (int im = 0; im < 4; im++) {
            int r0 = row_base + im * 16;
            float2 v0 = make_float2(c[im][in_][0] + b2.x, c[im][in_][1] + b2.y);
            float2 v1 = make_float2(c[im][in_][2] + b2.x, c[im][in_][3] + b2.y);
            *reinterpret_cast<float2*>(out + (size_t)r0 * NDIM + col) = v0;
            *reinterpret_cast<float2*>(out + (size_t)(r0 + 8) * NDIM + col) = v1;
        }
    }
}

// ============================================================================
// Host side
// ============================================================================

typedef CUresult (*PFN_encodeTiled_t)(
    CUtensorMap*, CUtensorMapDataType, cuuint32_t, void*,
    const cuuint64_t*, const cuuint64_t*, const cuuint32_t*, const cuuint32_t*,
    CUtensorMapInterleave, CUtensorMapSwizzle, CUtensorMapL2promotion,
    CUtensorMapFloatOOBfill);

extern "C" void kernel_launch(void* const* d_in, const int* in_sizes, int n_in,
                              void* d_out, int out_size) {
    const float* vals   = (const float*)d_in[0];
    const int*   rows   = (const int*)d_in[1];
    const int*   cols   = (const int*)d_in[2];
    const float* weight = (const float*)d_in[3];
    const float* bias   = (const float*)d_in[4];
    int nnz = in_sizes[0];

    void* pA = nullptr;
    void* pW = nullptr;
    cudaGetSymbolAddress(&pA, g_A);
    cudaGetSymbolAddress(&pW, g_W);

    PFN_encodeTiled_t encode = nullptr;
    cudaDriverEntryPointQueryResult qres;
    cudaGetDriverEntryPoint("cuTensorMapEncodeTiled", (void**)&encode,
                            cudaEnableDefault, &qres);

    CUtensorMap tmA, tmB;
    {
        cuuint64_t dims[2]    = {(cuuint64_t)KDIM, (cuuint64_t)MDIM};
        cuuint64_t strides[1] = {(cuuint64_t)KDIM * sizeof(__half)};
        cuuint32_t box[2]     = {(cuuint32_t)BK, (cuuint32_t)BM};
        cuuint32_t es[2]      = {1, 1};
        encode(&tmA, CU_TENSOR_MAP_DATA_TYPE_FLOAT16, 2, pA, dims, strides, box, es,
               CU_TENSOR_MAP_INTERLEAVE_NONE, CU_TENSOR_MAP_SWIZZLE_128B,
               CU_TENSOR_MAP_L2_PROMOTION_L2_128B, CU_TENSOR_MAP_FLOAT_OOB_FILL_NONE);
    }
    {
        cuuint64_t dims[2]    = {(cuuint64_t)KDIM, (cuuint64_t)NDIM};
        cuuint64_t strides[1] = {(cuuint64_t)KDIM * sizeof(__half)};
        cuuint32_t box[2]     = {(cuuint32_t)BK, (cuuint32_t)BN};
        cuuint32_t es[2]      = {1, 1};
        encode(&tmB, CU_TENSOR_MAP_DATA_TYPE_FLOAT16, 2, pW, dims, strides, box, es,
               CU_TENSOR_MAP_INTERLEAVE_NONE, CU_TENSOR_MAP_SWIZZLE_128B,
               CU_TENSOR_MAP_L2_PROMOTION_L2_128B, CU_TENSOR_MAP_FLOAT_OOB_FILL_NONE);
    }

    zero_a_kernel<<<2048, 256>>>();
    convert_w_kernel<<<2048, 256>>>(weight);
    if (nnz > 0)
        scatter_kernel<<<(nnz + 255) / 256, 256>>>(vals, rows, cols, nnz);

    cudaFuncSetAttribute(gemm_f16_kernel,
                         cudaFuncAttributeMaxDynamicSharedMemorySize, SMEM_TOTAL);
    gemm_f16_kernel<<<dim3(NDIM / BN, MDIM / BM), NTHREADS, SMEM_TOTAL>>>(
        tmA, tmB, bias, (float*)d_out);
}

// round 4
// speedup vs baseline: 1.0017x; 1.0017x over previous
#include <cuda_runtime.h>
#include <cuda_fp16.h>
#include <cuda.h>
#include <cstdint>

// ============================================================================
// out[8192,4096] = densify(COO) @ W^T + bias
// fp16 densify + TMA/mbarrier pipeline + mma.sync with fragment double-buffer.
// (tcgen05 unavailable: harness ptxas target is plain sm_103.)
// ============================================================================

static constexpr int MDIM = 8192;
static constexpr int NDIM = 4096;
static constexpr int KDIM = 4096;

static constexpr int BM = 128;
static constexpr int BN = 128;
static constexpr int BK = 128;             // per stage; 2 x 64-col SW128 blocks
static constexpr int STAGES = 3;
static constexpr int KITERS = KDIM / BK;   // 32

static constexpr int NTHREADS = 288;       // 8 compute warps + 1 producer warp

// Device-global scratch (no allocation allowed)
__device__ __half g_A[(size_t)MDIM * KDIM];   // 64 MB densified fp16 A
__device__ __half g_W[(size_t)NDIM * KDIM];   // 32 MB fp16 weight

// ----- SMEM layout -----
static constexpr int OFF_FULL  = 0;                      // 3 mbarriers
static constexpr int OFF_EMPTY = 32;                     // 3 mbarriers
static constexpr int OFF_A     = 1024;
static constexpr int HALF_BYTES = 128 * 64 * 2;          // 16384 (one 64-col block)
static constexpr int STAGE_A   = 2 * HALF_BYTES;         // 32768
static constexpr int OFF_B     = OFF_A + STAGES * STAGE_A;   // 99328
static constexpr int STAGE_B   = 2 * HALF_BYTES;         // 32768
static constexpr int SMEM_TOTAL = OFF_B + STAGES * STAGE_B;  // 197632

#define DEV_INLINE __device__ __forceinline__

DEV_INLINE uint32_t smem_u32(const void* p) {
    uint32_t a;
    asm("{ .reg .u64 t; cvta.to.shared.u64 t, %1; cvt.u32.u64 %0, t; }" : "=r"(a) : "l"(p));
    return a;
}

DEV_INLINE void mbar_init(uint32_t mbar, uint32_t count) {
    asm volatile("mbarrier.init.shared.b64 [%0], %1;" :: "r"(mbar), "r"(count) : "memory");
}

DEV_INLINE void mbar_expect_tx(uint32_t mbar, uint32_t bytes) {
    asm volatile("mbarrier.arrive.expect_tx.shared.b64 _, [%0], %1;"
                 :: "r"(mbar), "r"(bytes) : "memory");
}

DEV_INLINE void mbar_arrive(uint32_t mbar) {
    asm volatile("mbarrier.arrive.shared.b64 _, [%0];" :: "r"(mbar) : "memory");
}

DEV_INLINE void mbar_wait(uint32_t mbar, uint32_t parity) {
    asm volatile(
        "{\n\t.reg .pred P;\n\t"
        "W_%=:\n\t"
        "mbarrier.try_wait.parity.acquire.cta.shared::cta.b64 P, [%0], %1, 0x989680;\n\t"
        "@P bra.uni D_%=;\n\t"
        "bra.uni W_%=;\n\t"
        "D_%=:\n\t}"
        :: "r"(mbar), "r"(parity) : "memory");
}

DEV_INLINE void mbar_wait_relaxed(uint32_t mbar, uint32_t parity) {
    asm volatile(
        "{\n\t.reg .pred P;\n\t"
        "W_%=:\n\t"
        "mbarrier.try_wait.parity.relaxed.cta.shared::cta.b64 P, [%0], %1, 0x989680;\n\t"
        "@P bra.uni D_%=;\n\t"
        "bra.uni W_%=;\n\t"
        "D_%=:\n\t}"
        :: "r"(mbar), "r"(parity) : "memory");
}

DEV_INLINE void tma_load_2d(uint32_t dst, const CUtensorMap* map, int x, int y, uint32_t mbar) {
    asm volatile(
        "cp.async.bulk.tensor.2d.shared::cta.global.tile.mbarrier::complete_tx::bytes "
        "[%0], [%1, {%2, %3}], [%4];"
        :: "r"(dst), "l"(map), "r"(x), "r"(y), "r"(mbar) : "memory");
}

DEV_INLINE void ldsm_x4(uint32_t& r0, uint32_t& r1, uint32_t& r2, uint32_t& r3, uint32_t addr) {
    asm volatile("ldmatrix.sync.aligned.m8n8.x4.shared.b16 {%0, %1, %2, %3}, [%4];"
                 : "=r"(r0), "=r"(r1), "=r"(r2), "=r"(r3) : "r"(addr));
}

DEV_INLINE void mma_16816(float& d0, float& d1, float& d2, float& d3,
                          uint32_t a0, uint32_t a1, uint32_t a2, uint32_t a3,
                          uint32_t b0, uint32_t b1) {
    asm volatile(
        "mma.sync.aligned.m16n8k16.row.col.f32.f16.f16.f32 "
        "{%0, %1, %2, %3}, {%4, %5, %6, %7}, {%8, %9}, {%0, %1, %2, %3};"
        : "+f"(d0), "+f"(d1), "+f"(d2), "+f"(d3)
        : "r"(a0), "r"(a1), "r"(a2), "r"(a3), "r"(b0), "r"(b1));
}

// ============================================================================
// Prep kernels
// ============================================================================

// Fused: zero A (64MB) + convert W fp32->fp16 (reads 64MB, writes 32MB)
__global__ void prep_kernel(const float* __restrict__ w) {
    size_t gstride = (size_t)gridDim.x * blockDim.x;
    size_t g = (size_t)blockIdx.x * blockDim.x + threadIdx.x;

    size_t nA = (size_t)MDIM * KDIM * 2 / 16;   // uint4 count in A
    uint4* pa = reinterpret_cast<uint4*>(g_A);
    uint4 z = make_uint4(0, 0, 0, 0);
    for (size_t i = g; i < nA; i += gstride) pa[i] = z;

    size_t nW = (size_t)NDIM * KDIM / 4;        // float4 -> half2x2 groups
    const float4* src = reinterpret_cast<const float4*>(w);
    __half2* dst = reinterpret_cast<__half2*>(g_W);
    for (size_t i = g; i < nW; i += gstride) {
        float4 f = src[i];
        dst[2 * i]     = __floats2half2_rn(f.x, f.y);
        dst[2 * i + 1] = __floats2half2_rn(f.z, f.w);
    }
}

__global__ void scatter_kernel(const float* __restrict__ vals,
                               const int* __restrict__ rows,
                               const int* __restrict__ cols, int nnz) {
    int i = blockIdx.x * blockDim.x + threadIdx.x;
    if (i < nnz) {
        size_t idx = (size_t)rows[i] * KDIM + cols[i];
        atomicAdd(&g_A[idx], __float2half_rn(vals[i]));
    }
}

// ============================================================================
// GEMM kernel: TMA producer warp + 8 mma.sync compute warps.
// Warp grid 2(m) x 4(n): warp tile 64x32. Fragment double-buffering: LDSM for
// k16 step t+1 issued while mma for step t executes (incl. across stages).
// ============================================================================

struct FragA { uint32_t r[4][4]; };   // [im][reg]
struct FragB { uint32_t r[2][4]; };   // [jn][reg]

__global__ void __launch_bounds__(NTHREADS, 1) gemm_f16_kernel(
    const __grid_constant__ CUtensorMap tmA,
    const __grid_constant__ CUtensorMap tmB,
    const float* __restrict__ bias,
    float* __restrict__ out)
{
    extern __shared__ char smem[];
    uint32_t sb = smem_u32(smem);
    int tid = threadIdx.x;
    int wid = tid >> 5;
    int lid = tid & 31;
    int m0 = blockIdx.y * BM;
    int n0 = blockIdx.x * BN;

    if (tid == 0) {
        for (int s = 0; s < STAGES; s++) {
            mbar_init(sb + OFF_FULL + s * 8, 1);    // producer expect_tx arrives
            mbar_init(sb + OFF_EMPTY + s * 8, 8);   // one arrive per compute warp
        }
    }
    __syncthreads();

    if (wid == 8) {
        // ---------------- TMA producer warp ----------------
        if (lid == 0) {
            int stage = 0, phase = 1;  // fresh empty barriers: parity-1 wait passes
            for (int it = 0; it < KITERS; ++it) {
                int k0 = it * BK;
                mbar_wait_relaxed(sb + OFF_EMPTY + stage * 8, phase);
                mbar_expect_tx(sb + OFF_FULL + stage * 8, STAGE_A + STAGE_B);
                uint32_t aDst = sb + OFF_A + stage * STAGE_A;
                uint32_t bDst = sb + OFF_B + stage * STAGE_B;
                tma_load_2d(aDst,              &tmA, k0,      m0, sb + OFF_FULL + stage * 8);
                tma_load_2d(aDst + HALF_BYTES, &tmA, k0 + 64, m0, sb + OFF_FULL + stage * 8);
                tma_load_2d(bDst,              &tmB, k0,      n0, sb + OFF_FULL + stage * 8);
                tma_load_2d(bDst + HALF_BYTES, &tmB, k0 + 64, n0, sb + OFF_FULL + stage * 8);
                if (++stage == STAGES) { stage = 0; phase ^= 1; }
            }
        }
        return;
    }

    // ---------------- compute warps ----------------
    int warp_m = wid >> 2;        // 0..1 -> row offset warp_m*64
    int warp_n = wid & 3;         // 0..3 -> col offset warp_n*32

    // ldmatrix per-lane address components (SW128: swz(r*128+u*16) = r*128 + ((u^(r&7))*16))
    int a_row0 = warp_m * 64 + ((lid >> 3) & 1) * 8 + (lid & 7);
    int a_kh   = lid >> 4;
    int a_x7   = lid & 7;
    int b_row0 = warp_n * 32 + (lid >> 4) * 8 + (lid & 7);
    int b_kh   = (lid >> 3) & 1;
    int b_x7   = lid & 7;

    // frag loader for (stage, s8) where s8 in 0..7 indexes k16 step within BK=128
    auto load_frags = [&](int stage, int s8, FragA& fa, FragB& fb) {
        int half = s8 >> 2;
        int s4   = s8 & 3;
        uint32_t aBase = sb + OFF_A + stage * STAGE_A + half * HALF_BYTES;
        uint32_t bBase = sb + OFF_B + stage * STAGE_B + half * HALF_BYTES;
        #pragma unroll
        for (int im = 0; im < 4; im++) {
            int row = a_row0 + im * 16;
            uint32_t addr = aBase + row * 128 + (((s4 * 2 + a_kh) ^ a_x7) << 4);
            ldsm_x4(fa.r[im][0], fa.r[im][1], fa.r[im][2], fa.r[im][3], addr);
        }
        #pragma unroll
        for (int jn = 0; jn < 2; jn++) {
            int row = b_row0 + jn * 16;
            uint32_t addr = bBase + row * 128 + (((s4 * 2 + b_kh) ^ b_x7) << 4);
            ldsm_x4(fb.r[jn][0], fb.r[jn][1], fb.r[jn][2], fb.r[jn][3], addr);
        }
    };

    float c[4][4][4];   // [im][n8][reg]
    #pragma unroll
    for (int i = 0; i < 4; i++)
        #pragma unroll
        for (int j = 0; j < 4; j++)
            #pragma unroll
            for (int k = 0; k < 4; k++)
                c[i][j][k] = 0.0f;

    FragA fa[2];
    FragB fb[2];

    int stage = 0, phase = 0;
    mbar_wait(sb + OFF_FULL, 0);
    load_frags(0, 0, fa[0], fb[0]);

    for (int it = 0; it < KITERS; ++it) {
        #pragma unroll
        for (int s8 = 0; s8 < 8; ++s8) {
            int cur = s8 & 1;        // KITERS*8 steps; 8 even -> cur=0 at each it start
            int nxt = cur ^ 1;

            // ---- prefetch fragments for the next k16 step ----
            if (s8 < 7) {
                load_frags(stage, s8 + 1, fa[nxt], fb[nxt]);
            } else if (it < KITERS - 1) {
                int ns = (stage + 1 == STAGES) ? 0 : stage + 1;
                int np = (stage + 1 == STAGES) ? (phase ^ 1) : phase;
                mbar_wait(sb + OFF_FULL + ns * 8, np);
                load_frags(ns, 0, fa[nxt], fb[nxt]);
            }

            // ---- 16 mma on current fragments ----
            #pragma unroll
            for (int im = 0; im < 4; im++)
                #pragma unroll
                for (int in_ = 0; in_ < 4; in_++) {
                    int j = in_ >> 1, p = (in_ & 1) * 2;
                    mma_16816(c[im][in_][0], c[im][in_][1], c[im][in_][2], c[im][in_][3],
                              fa[cur].r[im][0], fa[cur].r[im][1],
                              fa[cur].r[im][2], fa[cur].r[im][3],
                              fb[cur].r[j][p], fb[cur].r[j][p + 1]);
                }
        }
        // all LDSMs from this stage completed (their mmas consumed the regs)
        if (lid == 0) mbar_arrive(sb + OFF_EMPTY + stage * 8);
        if (++stage == STAGES) { stage = 0; phase ^= 1; }
    }

    // ---------------- epilogue: c + bias -> out ----------------
    int col_base = n0 + warp_n * 32 + (lid & 3) * 2;
    int row_base = m0 + warp_m * 64 + (lid >> 2);
    #pragma unroll
    for (int in_ = 0; in_ < 4; in_++) {
        int col = col_base + in_ * 8;
        float2 b2 = *reinterpret_cast<const float2*>(bias + col);
        #pragma unroll
        for (int im = 0; im < 4; im++) {
            int r0 = row_base + im * 16;
            float2 v0 = make_float2(c[im][in_][0] + b2.x, c[im][in_][1] + b2.y);
            float2 v1 = make_float2(c[im][in_][2] + b2.x, c[im][in_][3] + b2.y);
            *reinterpret_cast<float2*>(out + (size_t)r0 * NDIM + col) = v0;
            *reinterpret_cast<float2*>(out + (size_t)(r0 + 8) * NDIM + col) = v1;
        }
    }
}

// ============================================================================
// Host side
// ============================================================================

typedef CUresult (*PFN_encodeTiled_t)(
    CUtensorMap*, CUtensorMapDataType, cuuint32_t, void*,
    const cuuint64_t*, const cuuint64_t*, const cuuint32_t*, const cuuint32_t*,
    CUtensorMapInterleave, CUtensorMapSwizzle, CUtensorMapL2promotion,
    CUtensorMapFloatOOBfill);

extern "C" void kernel_launch(void* const* d_in, const int* in_sizes, int n_in,
                              void* d_out, int out_size) {
    const float* vals   = (const float*)d_in[0];
    const int*   rows   = (const int*)d_in[1];
    const int*   cols   = (const int*)d_in[2];
    const float* weight = (const float*)d_in[3];
    const float* bias   = (const float*)d_in[4];
    int nnz = in_sizes[0];

    void* pA = nullptr;
    void* pW = nullptr;
    cudaGetSymbolAddress(&pA, g_A);
    cudaGetSymbolAddress(&pW, g_W);

    PFN_encodeTiled_t encode = nullptr;
    cudaDriverEntryPointQueryResult qres;
    cudaGetDriverEntryPoint("cuTensorMapEncodeTiled", (void**)&encode,
                            cudaEnableDefault, &qres);

    CUtensorMap tmA, tmB;
    {
        cuuint64_t dims[2]    = {(cuuint64_t)KDIM, (cuuint64_t)MDIM};
        cuuint64_t strides[1] = {(cuuint64_t)KDIM * sizeof(__half)};
        cuuint32_t box[2]     = {64, (cuuint32_t)BM};
        cuuint32_t es[2]      = {1, 1};
        encode(&tmA, CU_TENSOR_MAP_DATA_TYPE_FLOAT16, 2, pA, dims, strides, box, es,
               CU_TENSOR_MAP_INTERLEAVE_NONE, CU_TENSOR_MAP_SWIZZLE_128B,
               CU_TENSOR_MAP_L2_PROMOTION_L2_128B, CU_TENSOR_MAP_FLOAT_OOB_FILL_NONE);
    }
    {
        cuuint64_t dims[2]    = {(cuuint64_t)KDIM, (cuuint64_t)NDIM};
        cuuint64_t strides[1] = {(cuuint64_t)KDIM * sizeof(__half)};
        cuuint32_t box[2]     = {64, (cuuint32_t)BN};
        cuuint32_t es[2]      = {1, 1};
        encode(&tmB, CU_TENSOR_MAP_DATA_TYPE_FLOAT16, 2, pW, dims, strides, box, es,
               CU_TENSOR_MAP_INTERLEAVE_NONE, CU_TENSOR_MAP_SWIZZLE_128B,
               CU_TENSOR_MAP_L2_PROMOTION_L2_128B, CU_TENSOR_MAP_FLOAT_OOB_FILL_NONE);
    }

    prep_kernel<<<1184, 256>>>(weight);
    if (nnz > 0)
        scatter_kernel<<<(nnz + 255) / 256, 256>>>(vals, rows, cols, nnz);

    cudaFuncSetAttribute(gemm_f16_kernel,
                         cudaFuncAttributeMaxDynamicSharedMemorySize, SMEM_TOTAL);
    gemm_f16_kernel<<<dim3(NDIM / BN, MDIM / BM), NTHREADS, SMEM_TOTAL>>>(
        tmA, tmB, bias, (float*)d_out);
}

// round 5
// speedup vs baseline: 1.0309x; 1.0291x over previous
#include <cuda_runtime.h>
#include <cuda_fp16.h>
#include <cuda.h>
#include <cstdint>

// ============================================================================
// out[8192,4096] = densify(COO) @ W^T + bias
// fp16 densify + persistent-CTA GEMM: TMA/mbarrier ring runs continuously
// across output tiles so epilogue/prologue overlap with the next tile's
// mainloop. (tcgen05 unavailable: harness ptxas target is plain sm_103.)
// ============================================================================

static constexpr int MDIM = 8192;
static constexpr int NDIM = 4096;
static constexpr int KDIM = 4096;

static constexpr int BM = 128;
static constexpr int BN = 128;
static constexpr int BK = 128;             // per stage; 2 x 64-col SW128 blocks
static constexpr int STAGES = 3;
static constexpr int KITERS = KDIM / BK;   // 32

static constexpr int NTILES_X = NDIM / BN; // 32
static constexpr int NTILES   = (MDIM / BM) * NTILES_X;  // 2048
static constexpr int GRID     = 148;       // persistent: one CTA per SM

static constexpr int NTHREADS = 288;       // 8 compute warps + 1 producer warp

// Device-global scratch (no allocation allowed)
__device__ __half g_A[(size_t)MDIM * KDIM];   // 64 MB densified fp16 A
__device__ __half g_W[(size_t)NDIM * KDIM];   // 32 MB fp16 weight

// ----- SMEM layout -----
static constexpr int OFF_FULL  = 0;                      // 3 mbarriers
static constexpr int OFF_EMPTY = 32;                     // 3 mbarriers
static constexpr int OFF_A     = 1024;
static constexpr int HALF_BYTES = 128 * 64 * 2;          // 16384 (one 64-col block)
static constexpr int STAGE_A   = 2 * HALF_BYTES;         // 32768
static constexpr int OFF_B     = OFF_A + STAGES * STAGE_A;   // 99328
static constexpr int STAGE_B   = 2 * HALF_BYTES;         // 32768
static constexpr int SMEM_TOTAL = OFF_B + STAGES * STAGE_B;  // 197632

#define DEV_INLINE __device__ __forceinline__

DEV_INLINE uint32_t smem_u32(const void* p) {
    uint32_t a;
    asm("{ .reg .u64 t; cvta.to.shared.u64 t, %1; cvt.u32.u64 %0, t; }" : "=r"(a) : "l"(p));
    return a;
}

DEV_INLINE void mbar_init(uint32_t mbar, uint32_t count) {
    asm volatile("mbarrier.init.shared.b64 [%0], %1;" :: "r"(mbar), "r"(count) : "memory");
}

DEV_INLINE void mbar_expect_tx(uint32_t mbar, uint32_t bytes) {
    asm volatile("mbarrier.arrive.expect_tx.shared.b64 _, [%0], %1;"
                 :: "r"(mbar), "r"(bytes) : "memory");
}

DEV_INLINE void mbar_arrive(uint32_t mbar) {
    asm volatile("mbarrier.arrive.shared.b64 _, [%0];" :: "r"(mbar) : "memory");
}

DEV_INLINE void mbar_wait(uint32_t mbar, uint32_t parity) {
    asm volatile(
        "{\n\t.reg .pred P;\n\t"
        "W_%=:\n\t"
        "mbarrier.try_wait.parity.acquire.cta.shared::cta.b64 P, [%0], %1, 0x989680;\n\t"
        "@P bra.uni D_%=;\n\t"
        "bra.uni W_%=;\n\t"
        "D_%=:\n\t}"
        :: "r"(mbar), "r"(parity) : "memory");
}

DEV_INLINE void mbar_wait_relaxed(uint32_t mbar, uint32_t parity) {
    asm volatile(
        "{\n\t.reg .pred P;\n\t"
        "W_%=:\n\t"
        "mbarrier.try_wait.parity.relaxed.cta.shared::cta.b64 P, [%0], %1, 0x989680;\n\t"
        "@P bra.uni D_%=;\n\t"
        "bra.uni W_%=;\n\t"
        "D_%=:\n\t}"
        :: "r"(mbar), "r"(parity) : "memory");
}

DEV_INLINE void tma_load_2d(uint32_t dst, const CUtensorMap* map, int x, int y, uint32_t mbar) {
    asm volatile(
        "cp.async.bulk.tensor.2d.shared::cta.global.tile.mbarrier::complete_tx::bytes "
        "[%0], [%1, {%2, %3}], [%4];"
        :: "r"(dst), "l"(map), "r"(x), "r"(y), "r"(mbar) : "memory");
}

DEV_INLINE void ldsm_x4(uint32_t& r0, uint32_t& r1, uint32_t& r2, uint32_t& r3, uint32_t addr) {
    asm volatile("ldmatrix.sync.aligned.m8n8.x4.shared.b16 {%0, %1, %2, %3}, [%4];"
                 : "=r"(r0), "=r"(r1), "=r"(r2), "=r"(r3) : "r"(addr));
}

DEV_INLINE void mma_16816(float& d0, float& d1, float& d2, float& d3,
                          uint32_t a0, uint32_t a1, uint32_t a2, uint32_t a3,
                          uint32_t b0, uint32_t b1) {
    asm volatile(
        "mma.sync.aligned.m16n8k16.row.col.f32.f16.f16.f32 "
        "{%0, %1, %2, %3}, {%4, %5, %6, %7}, {%8, %9}, {%0, %1, %2, %3};"
        : "+f"(d0), "+f"(d1), "+f"(d2), "+f"(d3)
        : "r"(a0), "r"(a1), "r"(a2), "r"(a3), "r"(b0), "r"(b1));
}

// ============================================================================
// Prep kernels
// ============================================================================

// Fused: zero A (64MB) + convert W fp32->fp16
__global__ void prep_kernel(const float* __restrict__ w) {
    size_t gstride = (size_t)gridDim.x * blockDim.x;
    size_t g = (size_t)blockIdx.x * blockDim.x + threadIdx.x;

    size_t nA = (size_t)MDIM * KDIM * 2 / 16;   // uint4 count in A
    uint4* pa = reinterpret_cast<uint4*>(g_A);
    uint4 z = make_uint4(0, 0, 0, 0);
    for (size_t i = g; i < nA; i += gstride) pa[i] = z;

    size_t nW = (size_t)NDIM * KDIM / 4;        // float4 groups
    const float4* src = reinterpret_cast<const float4*>(w);
    __half2* dst = reinterpret_cast<__half2*>(g_W);
    for (size_t i = g; i < nW; i += gstride) {
        float4 f = src[i];
        dst[2 * i]     = __floats2half2_rn(f.x, f.y);
        dst[2 * i + 1] = __floats2half2_rn(f.z, f.w);
    }
}

__global__ void scatter_kernel(const float* __restrict__ vals,
                               const int* __restrict__ rows,
                               const int* __restrict__ cols, int nnz) {
    int i = blockIdx.x * blockDim.x + threadIdx.x;
    if (i < nnz) {
        size_t idx = (size_t)rows[i] * KDIM + cols[i];
        atomicAdd(&g_A[idx], __float2half_rn(vals[i]));
    }
}

// ============================================================================
// Persistent GEMM kernel: 1 producer warp + 8 compute warps per CTA; each CTA
// loops output tiles. The mbarrier ring never drains between tiles, so the
// producer fills tile t+1 while compute warps run tile t's epilogue.
// ============================================================================

struct FragA { uint32_t r[4][4]; };
struct FragB { uint32_t r[2][4]; };

__global__ void __launch_bounds__(NTHREADS, 1) gemm_f16_kernel(
    const __grid_constant__ CUtensorMap tmA,
    const __grid_constant__ CUtensorMap tmB,
    const float* __restrict__ bias,
    float* __restrict__ out)
{
    extern __shared__ char smem[];
    uint32_t sb = smem_u32(smem);
    int tid = threadIdx.x;
    int wid = tid >> 5;
    int lid = tid & 31;

    if (tid == 0) {
        for (int s = 0; s < STAGES; s++) {
            mbar_init(sb + OFF_FULL + s * 8, 1);    // producer expect_tx arrives
            mbar_init(sb + OFF_EMPTY + s * 8, 8);   // one arrive per compute warp
        }
    }
    __syncthreads();

    if (wid == 8) {
        // ---------------- TMA producer warp (persistent) ----------------
        if (lid == 0) {
            int stage = 0, phase = 1;  // fresh empty barriers: parity-1 wait passes
            for (int t = blockIdx.x; t < NTILES; t += GRID) {
                int m0 = (t / NTILES_X) * BM;
                int n0 = (t % NTILES_X) * BN;
                for (int it = 0; it < KITERS; ++it) {
                    int k0 = it * BK;
                    mbar_wait_relaxed(sb + OFF_EMPTY + stage * 8, phase);
                    mbar_expect_tx(sb + OFF_FULL + stage * 8, STAGE_A + STAGE_B);
                    uint32_t aDst = sb + OFF_A + stage * STAGE_A;
                    uint32_t bDst = sb + OFF_B + stage * STAGE_B;
                    tma_load_2d(aDst,              &tmA, k0,      m0, sb + OFF_FULL + stage * 8);
                    tma_load_2d(aDst + HALF_BYTES, &tmA, k0 + 64, m0, sb + OFF_FULL + stage * 8);
                    tma_load_2d(bDst,              &tmB, k0,      n0, sb + OFF_FULL + stage * 8);
                    tma_load_2d(bDst + HALF_BYTES, &tmB, k0 + 64, n0, sb + OFF_FULL + stage * 8);
                    if (++stage == STAGES) { stage = 0; phase ^= 1; }
                }
            }
        }
        return;
    }

    // ---------------- compute warps (persistent) ----------------
    int warp_m = wid >> 2;        // 0..1 -> row offset warp_m*64
    int warp_n = wid & 3;         // 0..3 -> col offset warp_n*32

    // ldmatrix lane addressing (SW128: swz(r*128+u*16) = r*128 + ((u^(r&7))*16))
    int a_row0 = warp_m * 64 + ((lid >> 3) & 1) * 8 + (lid & 7);
    int a_kh   = lid >> 4;
    int a_x7   = lid & 7;
    int b_row0 = warp_n * 32 + (lid >> 4) * 8 + (lid & 7);
    int b_kh   = (lid >> 3) & 1;
    int b_x7   = lid & 7;

    auto load_frags = [&](int stage, int s8, FragA& fa, FragB& fb) {
        int half = s8 >> 2;
        int s4   = s8 & 3;
        uint32_t aBase = sb + OFF_A + stage * STAGE_A + half * HALF_BYTES;
        uint32_t bBase = sb + OFF_B + stage * STAGE_B + half * HALF_BYTES;
        #pragma unroll
        for (int im = 0; im < 4; im++) {
            int row = a_row0 + im * 16;
            uint32_t addr = aBase + row * 128 + (((s4 * 2 + a_kh) ^ a_x7) << 4);
            ldsm_x4(fa.r[im][0], fa.r[im][1], fa.r[im][2], fa.r[im][3], addr);
        }
        #pragma unroll
        for (int jn = 0; jn < 2; jn++) {
            int row = b_row0 + jn * 16;
            uint32_t addr = bBase + row * 128 + (((s4 * 2 + b_kh) ^ b_x7) << 4);
            ldsm_x4(fb.r[jn][0], fb.r[jn][1], fb.r[jn][2], fb.r[jn][3], addr);
        }
    };

    int stage = 0, phase = 0;

    for (int t = blockIdx.x; t < NTILES; t += GRID) {
        int m0 = (t / NTILES_X) * BM;
        int n0 = (t % NTILES_X) * BN;

        float c[4][4][4];   // [im][n8][reg]
        #pragma unroll
        for (int i = 0; i < 4; i++)
            #pragma unroll
            for (int j = 0; j < 4; j++)
                #pragma unroll
                for (int k = 0; k < 4; k++)
                    c[i][j][k] = 0.0f;

        FragA fa[2];
        FragB fb[2];

        // tile prologue: wait first stage of this tile, load first frags
        mbar_wait(sb + OFF_FULL + stage * 8, phase);
        load_frags(stage, 0, fa[0], fb[0]);

        for (int it = 0; it < KITERS; ++it) {
            #pragma unroll
            for (int s8 = 0; s8 < 8; ++s8) {
                int cur = s8 & 1;
                int nxt = cur ^ 1;

                // prefetch fragments for the next k16 step (within this tile)
                if (s8 < 7) {
                    load_frags(stage, s8 + 1, fa[nxt], fb[nxt]);
                } else if (it < KITERS - 1) {
                    int ns = (stage + 1 == STAGES) ? 0 : stage + 1;
                    int np = (stage + 1 == STAGES) ? (phase ^ 1) : phase;
                    mbar_wait(sb + OFF_FULL + ns * 8, np);
                    load_frags(ns, 0, fa[nxt], fb[nxt]);
                }

                #pragma unroll
                for (int im = 0; im < 4; im++)
                    #pragma unroll
                    for (int in_ = 0; in_ < 4; in_++) {
                        int j = in_ >> 1, p = (in_ & 1) * 2;
                        mma_16816(c[im][in_][0], c[im][in_][1], c[im][in_][2], c[im][in_][3],
                                  fa[cur].r[im][0], fa[cur].r[im][1],
                                  fa[cur].r[im][2], fa[cur].r[im][3],
                                  fb[cur].r[j][p], fb[cur].r[j][p + 1]);
                    }
            }
            // release this stage BEFORE the epilogue so the producer keeps going
            if (lid == 0) mbar_arrive(sb + OFF_EMPTY + stage * 8);
            if (++stage == STAGES) { stage = 0; phase ^= 1; }
        }

        // ---- epilogue (overlaps with producer filling next tile) ----
        int col_base = n0 + warp_n * 32 + (lid & 3) * 2;
        int row_base = m0 + warp_m * 64 + (lid >> 2);
        #pragma unroll
        for (int in_ = 0; in_ < 4; in_++) {
            int col = col_base + in_ * 8;
            float2 b2 = *reinterpret_cast<const float2*>(bias + col);
            #pragma unroll
            for (int im = 0; im < 4; im++) {
                int r0 = row_base + im * 16;
                float2 v0 = make_float2(c[im][in_][0] + b2.x, c[im][in_][1] + b2.y);
                float2 v1 = make_float2(c[im][in_][2] + b2.x, c[im][in_][3] + b2.y);
                *reinterpret_cast<float2*>(out + (size_t)r0 * NDIM + col) = v0;
                *reinterpret_cast<float2*>(out + (size_t)(r0 + 8) * NDIM + col) = v1;
            }
        }
    }
}

// ============================================================================
// Host side
// ============================================================================

typedef CUresult (*PFN_encodeTiled_t)(
    CUtensorMap*, CUtensorMapDataType, cuuint32_t, void*,
    const cuuint64_t*, const cuuint64_t*, const cuuint32_t*, const cuuint32_t*,
    CUtensorMapInterleave, CUtensorMapSwizzle, CUtensorMapL2promotion,
    CUtensorMapFloatOOBfill);

extern "C" void kernel_launch(void* const* d_in, const int* in_sizes, int n_in,
                              void* d_out, int out_size) {
    const float* vals   = (const float*)d_in[0];
    const int*   rows   = (const int*)d_in[1];
    const int*   cols   = (const int*)d_in[2];
    const float* weight = (const float*)d_in[3];
    const float* bias   = (const float*)d_in[4];
    int nnz = in_sizes[0];

    void* pA = nullptr;
    void* pW = nullptr;
    cudaGetSymbolAddress(&pA, g_A);
    cudaGetSymbolAddress(&pW, g_W);

    PFN_encodeTiled_t encode = nullptr;
    cudaDriverEntryPointQueryResult qres;
    cudaGetDriverEntryPoint("cuTensorMapEncodeTiled", (void**)&encode,
                            cudaEnableDefault, &qres);

    CUtensorMap tmA, tmB;
    {
        cuuint64_t dims[2]    = {(cuuint64_t)KDIM, (cuuint64_t)MDIM};
        cuuint64_t strides[1] = {(cuuint64_t)KDIM * sizeof(__half)};
        cuuint32_t box[2]     = {64, (cuuint32_t)BM};
        cuuint32_t es[2]      = {1, 1};
        encode(&tmA, CU_TENSOR_MAP_DATA_TYPE_FLOAT16, 2, pA, dims, strides, box, es,
               CU_TENSOR_MAP_INTERLEAVE_NONE, CU_TENSOR_MAP_SWIZZLE_128B,
               CU_TENSOR_MAP_L2_PROMOTION_L2_128B, CU_TENSOR_MAP_FLOAT_OOB_FILL_NONE);
    }
    {
        cuuint64_t dims[2]    = {(cuuint64_t)KDIM, (cuuint64_t)NDIM};
        cuuint64_t strides[1] = {(cuuint64_t)KDIM * sizeof(__half)};
        cuuint32_t box[2]     = {64, (cuuint32_t)BN};
        cuuint32_t es[2]      = {1, 1};
        encode(&tmB, CU_TENSOR_MAP_DATA_TYPE_FLOAT16, 2, pW, dims, strides, box, es,
               CU_TENSOR_MAP_INTERLEAVE_NONE, CU_TENSOR_MAP_SWIZZLE_128B,
               CU_TENSOR_MAP_L2_PROMOTION_L2_128B, CU_TENSOR_MAP_FLOAT_OOB_FILL_NONE);
    }

    prep_kernel<<<1184, 256>>>(weight);
    if (nnz > 0)
        scatter_kernel<<<(nnz + 255) / 256, 256>>>(vals, rows, cols, nnz);

    cudaFuncSetAttribute(gemm_f16_kernel,
                         cudaFuncAttributeMaxDynamicSharedMemorySize, SMEM_TOTAL);
    gemm_f16_kernel<<<GRID, NTHREADS, SMEM_TOTAL>>>(tmA, tmB, bias, (float*)d_out);
}

// round 6
// speedup vs baseline: 1.0327x; 1.0018x over previous
#include <cuda_runtime.h>
#include <cuda_fp16.h>
#include <cuda.h>
#include <cstdint>

// ============================================================================
// out[8192,4096] = densify(COO) @ W^T + bias
// fp16 densify + persistent-CTA GEMM, TMA/mbarrier ring continuous across
// tiles. R5: staggered stage-waits between co-SMSP warps + cross-tile
// fragment prefetch (no uncovered TRYWAIT anywhere in steady state).
// ============================================================================

static constexpr int MDIM = 8192;
static constexpr int NDIM = 4096;
static constexpr int KDIM = 4096;

static constexpr int BM = 128;
static constexpr int BN = 128;
static constexpr int BK = 128;             // per stage; 2 x 64-col SW128 blocks
static constexpr int STAGES = 3;
static constexpr int KITERS = KDIM / BK;   // 32

static constexpr int NTILES_X = NDIM / BN; // 32
static constexpr int NTILES   = (MDIM / BM) * NTILES_X;  // 2048
static constexpr int GRID     = 148;       // persistent: one CTA per SM

static constexpr int NTHREADS = 288;       // 8 compute warps + 1 producer warp

// Device-global scratch (no allocation allowed)
__device__ __half g_A[(size_t)MDIM * KDIM];   // 64 MB densified fp16 A
__device__ __half g_W[(size_t)NDIM * KDIM];   // 32 MB fp16 weight

// ----- SMEM layout -----
static constexpr int OFF_FULL  = 0;                      // 3 mbarriers
static constexpr int OFF_EMPTY = 32;                     // 3 mbarriers
static constexpr int OFF_A     = 1024;
static constexpr int HALF_BYTES = 128 * 64 * 2;          // 16384 (one 64-col block)
static constexpr int STAGE_A   = 2 * HALF_BYTES;         // 32768
static constexpr int OFF_B     = OFF_A + STAGES * STAGE_A;   // 99328
static constexpr int STAGE_B   = 2 * HALF_BYTES;         // 32768
static constexpr int SMEM_TOTAL = OFF_B + STAGES * STAGE_B;  // 197632

#define DEV_INLINE __device__ __forceinline__

DEV_INLINE uint32_t smem_u32(const void* p) {
    uint32_t a;
    asm("{ .reg .u64 t; cvta.to.shared.u64 t, %1; cvt.u32.u64 %0, t; }" : "=r"(a) : "l"(p));
    return a;
}

DEV_INLINE void mbar_init(uint32_t mbar, uint32_t count) {
    asm volatile("mbarrier.init.shared.b64 [%0], %1;" :: "r"(mbar), "r"(count) : "memory");
}

DEV_INLINE void mbar_expect_tx(uint32_t mbar, uint32_t bytes) {
    asm volatile("mbarrier.arrive.expect_tx.shared.b64 _, [%0], %1;"
                 :: "r"(mbar), "r"(bytes) : "memory");
}

DEV_INLINE void mbar_arrive(uint32_t mbar) {
    asm volatile("mbarrier.arrive.shared.b64 _, [%0];" :: "r"(mbar) : "memory");
}

DEV_INLINE void mbar_wait(uint32_t mbar, uint32_t parity) {
    asm volatile(
        "{\n\t.reg .pred P;\n\t"
        "W_%=:\n\t"
        "mbarrier.try_wait.parity.acquire.cta.shared::cta.b64 P, [%0], %1, 0x989680;\n\t"
        "@P bra.uni D_%=;\n\t"
        "bra.uni W_%=;\n\t"
        "D_%=:\n\t}"
        :: "r"(mbar), "r"(parity) : "memory");
}

DEV_INLINE void mbar_wait_relaxed(uint32_t mbar, uint32_t parity) {
    asm volatile(
        "{\n\t.reg .pred P;\n\t"
        "W_%=:\n\t"
        "mbarrier.try_wait.parity.relaxed.cta.shared::cta.b64 P, [%0], %1, 0x989680;\n\t"
        "@P bra.uni D_%=;\n\t"
        "bra.uni W_%=;\n\t"
        "D_%=:\n\t}"
        :: "r"(mbar), "r"(parity) : "memory");
}

DEV_INLINE void tma_load_2d(uint32_t dst, const CUtensorMap* map, int x, int y, uint32_t mbar) {
    asm volatile(
        "cp.async.bulk.tensor.2d.shared::cta.global.tile.mbarrier::complete_tx::bytes "
        "[%0], [%1, {%2, %3}], [%4];"
        :: "r"(dst), "l"(map), "r"(x), "r"(y), "r"(mbar) : "memory");
}

DEV_INLINE void ldsm_x4(uint32_t& r0, uint32_t& r1, uint32_t& r2, uint32_t& r3, uint32_t addr) {
    asm volatile("ldmatrix.sync.aligned.m8n8.x4.shared.b16 {%0, %1, %2, %3}, [%4];"
                 : "=r"(r0), "=r"(r1), "=r"(r2), "=r"(r3) : "r"(addr));
}

DEV_INLINE void mma_16816(float& d0, float& d1, float& d2, float& d3,
                          uint32_t a0, uint32_t a1, uint32_t a2, uint32_t a3,
                          uint32_t b0, uint32_t b1) {
    asm volatile(
        "mma.sync.aligned.m16n8k16.row.col.f32.f16.f16.f32 "
        "{%0, %1, %2, %3}, {%4, %5, %6, %7}, {%8, %9}, {%0, %1, %2, %3};"
        : "+f"(d0), "+f"(d1), "+f"(d2), "+f"(d3)
        : "r"(a0), "r"(a1), "r"(a2), "r"(a3), "r"(b0), "r"(b1));
}

// ============================================================================
// Prep kernels
// ============================================================================

__global__ void prep_kernel(const float* __restrict__ w) {
    size_t gstride = (size_t)gridDim.x * blockDim.x;
    size_t g = (size_t)blockIdx.x * blockDim.x + threadIdx.x;

    size_t nA = (size_t)MDIM * KDIM * 2 / 16;   // uint4 count in A
    uint4* pa = reinterpret_cast<uint4*>(g_A);
    uint4 z = make_uint4(0, 0, 0, 0);
    for (size_t i = g; i < nA; i += gstride) pa[i] = z;

    size_t nW = (size_t)NDIM * KDIM / 4;        // float4 groups
    const float4* src = reinterpret_cast<const float4*>(w);
    __half2* dst = reinterpret_cast<__half2*>(g_W);
    for (size_t i = g; i < nW; i += gstride) {
        float4 f = src[i];
        dst[2 * i]     = __floats2half2_rn(f.x, f.y);
        dst[2 * i + 1] = __floats2half2_rn(f.z, f.w);
    }
}

__global__ void scatter_kernel(const float* __restrict__ vals,
                               const int* __restrict__ rows,
                               const int* __restrict__ cols, int nnz) {
    int i = blockIdx.x * blockDim.x + threadIdx.x;
    if (i < nnz) {
        size_t idx = (size_t)rows[i] * KDIM + cols[i];
        atomicAdd(&g_A[idx], __float2half_rn(vals[i]));
    }
}

// ============================================================================
// Persistent GEMM kernel
// ============================================================================

struct FragA { uint32_t r[4][4]; };
struct FragB { uint32_t r[2][4]; };

__global__ void __launch_bounds__(NTHREADS, 1) gemm_f16_kernel(
    const __grid_constant__ CUtensorMap tmA,
    const __grid_constant__ CUtensorMap tmB,
    const float* __restrict__ bias,
    float* __restrict__ out)
{
    extern __shared__ char smem[];
    uint32_t sb = smem_u32(smem);
    int tid = threadIdx.x;
    int wid = tid >> 5;
    int lid = tid & 31;

    if (tid == 0) {
        for (int s = 0; s < STAGES; s++) {
            mbar_init(sb + OFF_FULL + s * 8, 1);    // producer expect_tx arrives
            mbar_init(sb + OFF_EMPTY + s * 8, 8);   // one arrive per compute warp
        }
    }
    __syncthreads();

    if (wid == 8) {
        // ---------------- TMA producer warp (persistent) ----------------
        if (lid == 0) {
            int stage = 0, phase = 1;
            for (int t = blockIdx.x; t < NTILES; t += GRID) {
                int m0 = (t / NTILES_X) * BM;
                int n0 = (t % NTILES_X) * BN;
                for (int it = 0; it < KITERS; ++it) {
                    int k0 = it * BK;
                    mbar_wait_relaxed(sb + OFF_EMPTY + stage * 8, phase);
                    mbar_expect_tx(sb + OFF_FULL + stage * 8, STAGE_A + STAGE_B);
                    uint32_t aDst = sb + OFF_A + stage * STAGE_A;
                    uint32_t bDst = sb + OFF_B + stage * STAGE_B;
                    tma_load_2d(aDst,              &tmA, k0,      m0, sb + OFF_FULL + stage * 8);
                    tma_load_2d(aDst + HALF_BYTES, &tmA, k0 + 64, m0, sb + OFF_FULL + stage * 8);
                    tma_load_2d(bDst,              &tmB, k0,      n0, sb + OFF_FULL + stage * 8);
                    tma_load_2d(bDst + HALF_BYTES, &tmB, k0 + 64, n0, sb + OFF_FULL + stage * 8);
                    if (++stage == STAGES) { stage = 0; phase ^= 1; }
                }
            }
        }
        return;
    }

    // ---------------- compute warps (persistent) ----------------
    int warp_m = wid >> 2;        // co-SMSP warps differ in warp_m
    int warp_n = wid & 3;

    // Staggered next-stage wait position: warp_m=0 -> s8==5, warp_m=1 -> s8==7.
    // While one co-warp is blocked in TRYWAIT (~90cy), the other still has
    // >=1 full mma batch queued on the shared tensor pipe.
    int wait_pos = warp_m ? 7 : 5;

    // ldmatrix lane addressing (SW128: swz(r*128+u*16) = r*128 + ((u^(r&7))*16))
    int a_row0 = warp_m * 64 + ((lid >> 3) & 1) * 8 + (lid & 7);
    int a_kh   = lid >> 4;
    int a_x7   = lid & 7;
    int b_row0 = warp_n * 32 + (lid >> 4) * 8 + (lid & 7);
    int b_kh   = (lid >> 3) & 1;
    int b_x7   = lid & 7;

    auto load_frags = [&](int stg, int s8, FragA& fa, FragB& fb) {
        int half = s8 >> 2;
        int s4   = s8 & 3;
        uint32_t aBase = sb + OFF_A + stg * STAGE_A + half * HALF_BYTES;
        uint32_t bBase = sb + OFF_B + stg * STAGE_B + half * HALF_BYTES;
        #pragma unroll
        for (int im = 0; im < 4; im++) {
            int row = a_row0 + im * 16;
            uint32_t addr = aBase + row * 128 + (((s4 * 2 + a_kh) ^ a_x7) << 4);
            ldsm_x4(fa.r[im][0], fa.r[im][1], fa.r[im][2], fa.r[im][3], addr);
        }
        #pragma unroll
        for (int jn = 0; jn < 2; jn++) {
            int row = b_row0 + jn * 16;
            uint32_t addr = bBase + row * 128 + (((s4 * 2 + b_kh) ^ b_x7) << 4);
            ldsm_x4(fb.r[jn][0], fb.r[jn][1], fb.r[jn][2], fb.r[jn][3], addr);
        }
    };

    FragA fa[2];
    FragB fb[2];
    int stage = 0, phase = 0;

    // one-time prologue: wait very first stage, load first fragments
    mbar_wait(sb + OFF_FULL, 0);
    load_frags(0, 0, fa[0], fb[0]);

    for (int t = blockIdx.x; t < NTILES; t += GRID) {
        int m0 = (t / NTILES_X) * BM;
        int n0 = (t % NTILES_X) * BN;
        bool last_tile = (t + GRID >= NTILES);

        float c[4][4][4];
        #pragma unroll
        for (int i = 0; i < 4; i++)
            #pragma unroll
            for (int j = 0; j < 4; j++)
                #pragma unroll
                for (int k = 0; k < 4; k++)
                    c[i][j][k] = 0.0f;

        for (int it = 0; it < KITERS; ++it) {
            bool has_next = !(last_tile && it == KITERS - 1);
            int ns = (stage + 1 == STAGES) ? 0 : stage + 1;
            int np = (stage + 1 == STAGES) ? (phase ^ 1) : phase;

            #pragma unroll
            for (int s8 = 0; s8 < 8; ++s8) {
                int cur = s8 & 1;
                int nxt = cur ^ 1;

                // staggered early wait for the NEXT stage (covered by mma below)
                if (s8 == wait_pos && has_next)
                    mbar_wait(sb + OFF_FULL + ns * 8, np);

                // prefetch fragments for the next k16 step
                if (s8 < 7) {
                    load_frags(stage, s8 + 1, fa[nxt], fb[nxt]);
                } else if (has_next) {
                    // next stage: either next kiter of this tile, or kiter 0 of
                    // the next tile (ring is continuous; producer knows coords)
                    load_frags(ns, 0, fa[nxt], fb[nxt]);
                }

                #pragma unroll
                for (int im = 0; im < 4; im++)
                    #pragma unroll
                    for (int in_ = 0; in_ < 4; in_++) {
                        int j = in_ >> 1, p = (in_ & 1) * 2;
                        mma_16816(c[im][in_][0], c[im][in_][1], c[im][in_][2], c[im][in_][3],
                                  fa[cur].r[im][0], fa[cur].r[im][1],
                                  fa[cur].r[im][2], fa[cur].r[im][3],
                                  fb[cur].r[j][p], fb[cur].r[j][p + 1]);
                    }
            }
            if (lid == 0) mbar_arrive(sb + OFF_EMPTY + stage * 8);
            if (++stage == STAGES) { stage = 0; phase ^= 1; }
        }

        // ---- epilogue (next tile's first fragments already in registers;
        //      producer keeps filling the ring underneath) ----
        int col_base = n0 + warp_n * 32 + (lid & 3) * 2;
        int row_base = m0 + warp_m * 64 + (lid >> 2);
        #pragma unroll
        for (int in_ = 0; in_ < 4; in_++) {
            int col = col_base + in_ * 8;
            float2 b2 = *reinterpret_cast<const float2*>(bias + col);
            #pragma unroll
            for (int im = 0; im < 4; im++) {
                int r0 = row_base + im * 16;
                float2 v0 = make_float2(c[im][in_][0] + b2.x, c[im][in_][1] + b2.y);
                float2 v1 = make_float2(c[im][in_][2] + b2.x, c[im][in_][3] + b2.y);
                *reinterpret_cast<float2*>(out + (size_t)r0 * NDIM + col) = v0;
                *reinterpret_cast<float2*>(out + (size_t)(r0 + 8) * NDIM + col) = v1;
            }
        }
    }
}

// ============================================================================
// Host side
// ============================================================================

typedef CUresult (*PFN_encodeTiled_t)(
    CUtensorMap*, CUtensorMapDataType, cuuint32_t, void*,
    const cuuint64_t*, const cuuint64_t*, const cuuint32_t*, const cuuint32_t*,
    CUtensorMapInterleave, CUtensorMapSwizzle, CUtensorMapL2promotion,
    CUtensorMapFloatOOBfill);

extern "C" void kernel_launch(void* const* d_in, const int* in_sizes, int n_in,
                              void* d_out, int out_size) {
    const float* vals   = (const float*)d_in[0];
    const int*   rows   = (const int*)d_in[1];
    const int*   cols   = (const int*)d_in[2];
    const float* weight = (const float*)d_in[3];
    const float* bias   = (const float*)d_in[4];
    int nnz = in_sizes[0];

    void* pA = nullptr;
    void* pW = nullptr;
    cudaGetSymbolAddress(&pA, g_A);
    cudaGetSymbolAddress(&pW, g_W);

    PFN_encodeTiled_t encode = nullptr;
    cudaDriverEntryPointQueryResult qres;
    cudaGetDriverEntryPoint("cuTensorMapEncodeTiled", (void**)&encode,
                            cudaEnableDefault, &qres);

    CUtensorMap tmA, tmB;
    {
        cuuint64_t dims[2]    = {(cuuint64_t)KDIM, (cuuint64_t)MDIM};
        cuuint64_t strides[1] = {(cuuint64_t)KDIM * sizeof(__half)};
        cuuint32_t box[2]     = {64, (cuuint32_t)BM};
        cuuint32_t es[2]      = {1, 1};
        encode(&tmA, CU_TENSOR_MAP_DATA_TYPE_FLOAT16, 2, pA, dims, strides, box, es,
               CU_TENSOR_MAP_INTERLEAVE_NONE, CU_TENSOR_MAP_SWIZZLE_128B,
               CU_TENSOR_MAP_L2_PROMOTION_L2_128B, CU_TENSOR_MAP_FLOAT_OOB_FILL_NONE);
    }
    {
        cuuint64_t dims[2]    = {(cuuint64_t)KDIM, (cuuint64_t)NDIM};
        cuuint64_t strides[1] = {(cuuint64_t)KDIM * sizeof(__half)};
        cuuint32_t box[2]     = {64, (cuuint32_t)BN};
        cuuint32_t es[2]      = {1, 1};
        encode(&tmB, CU_TENSOR_MAP_DATA_TYPE_FLOAT16, 2, pW, dims, strides, box, es,
               CU_TENSOR_MAP_INTERLEAVE_NONE, CU_TENSOR_MAP_SWIZZLE_128B,
               CU_TENSOR_MAP_L2_PROMOTION_L2_128B, CU_TENSOR_MAP_FLOAT_OOB_FILL_NONE);
    }

    prep_kernel<<<1184, 256>>>(weight);
    if (nnz > 0)
        scatter_kernel<<<(nnz + 255) / 256, 256>>>(vals, rows, cols, nnz);

    cudaFuncSetAttribute(gemm_f16_kernel,
                         cudaFuncAttributeMaxDynamicSharedMemorySize, SMEM_TOTAL);
    gemm_f16_kernel<<<GRID, NTHREADS, SMEM_TOTAL>>>(tmA, tmB, bias, (float*)d_out);
}

// round 7
// speedup vs baseline: 1.0410x; 1.0081x over previous
#include <cuda_runtime.h>
#include <cuda_fp16.h>
#include <cuda.h>
#include <cstdint>

// ============================================================================
// out[8192,4096] = densify(COO) @ W^T + bias
// R6: memsetAsync zero-A + fused (W-convert || REDG scatter) prep, persistent
// mma.sync GEMM unchanged. (tcgen05 unavailable: ptxas target plain sm_103.)
// ============================================================================

static constexpr int MDIM = 8192;
static constexpr int NDIM = 4096;
static constexpr int KDIM = 4096;

static constexpr int BM = 128;
static constexpr int BN = 128;
static constexpr int BK = 128;             // per stage; 2 x 64-col SW128 blocks
static constexpr int STAGES = 3;
static constexpr int KITERS = KDIM / BK;   // 32

static constexpr int NTILES_X = NDIM / BN; // 32
static constexpr int NTILES   = (MDIM / BM) * NTILES_X;  // 2048
static constexpr int GRID     = 148;       // persistent: one CTA per SM

static constexpr int NTHREADS = 288;       // 8 compute warps + 1 producer warp

// Fused prep kernel: first CONV_BLOCKS convert W, rest scatter.
static constexpr int PREP_BLOCKS = 1184;
static constexpr int CONV_BLOCKS = 704;

// Device-global scratch (no allocation allowed)
__device__ __half g_A[(size_t)MDIM * KDIM];   // 64 MB densified fp16 A
__device__ __half g_W[(size_t)NDIM * KDIM];   // 32 MB fp16 weight

// ----- SMEM layout -----
static constexpr int OFF_FULL  = 0;
static constexpr int OFF_EMPTY = 32;
static constexpr int OFF_A     = 1024;
static constexpr int HALF_BYTES = 128 * 64 * 2;          // 16384
static constexpr int STAGE_A   = 2 * HALF_BYTES;         // 32768
static constexpr int OFF_B     = OFF_A + STAGES * STAGE_A;
static constexpr int STAGE_B   = 2 * HALF_BYTES;
static constexpr int SMEM_TOTAL = OFF_B + STAGES * STAGE_B;  // 197632

#define DEV_INLINE __device__ __forceinline__

DEV_INLINE uint32_t smem_u32(const void* p) {
    uint32_t a;
    asm("{ .reg .u64 t; cvta.to.shared.u64 t, %1; cvt.u32.u64 %0, t; }" : "=r"(a) : "l"(p));
    return a;
}

DEV_INLINE void mbar_init(uint32_t mbar, uint32_t count) {
    asm volatile("mbarrier.init.shared.b64 [%0], %1;" :: "r"(mbar), "r"(count) : "memory");
}

DEV_INLINE void mbar_expect_tx(uint32_t mbar, uint32_t bytes) {
    asm volatile("mbarrier.arrive.expect_tx.shared.b64 _, [%0], %1;"
                 :: "r"(mbar), "r"(bytes) : "memory");
}

DEV_INLINE void mbar_arrive(uint32_t mbar) {
    asm volatile("mbarrier.arrive.shared.b64 _, [%0];" :: "r"(mbar) : "memory");
}

DEV_INLINE void mbar_wait(uint32_t mbar, uint32_t parity) {
    asm volatile(
        "{\n\t.reg .pred P;\n\t"
        "W_%=:\n\t"
        "mbarrier.try_wait.parity.acquire.cta.shared::cta.b64 P, [%0], %1, 0x989680;\n\t"
        "@P bra.uni D_%=;\n\t"
        "bra.uni W_%=;\n\t"
        "D_%=:\n\t}"
        :: "r"(mbar), "r"(parity) : "memory");
}

DEV_INLINE void mbar_wait_relaxed(uint32_t mbar, uint32_t parity) {
    asm volatile(
        "{\n\t.reg .pred P;\n\t"
        "W_%=:\n\t"
        "mbarrier.try_wait.parity.relaxed.cta.shared::cta.b64 P, [%0], %1, 0x989680;\n\t"
        "@P bra.uni D_%=;\n\t"
        "bra.uni W_%=;\n\t"
        "D_%=:\n\t}"
        :: "r"(mbar), "r"(parity) : "memory");
}

DEV_INLINE void tma_load_2d(uint32_t dst, const CUtensorMap* map, int x, int y, uint32_t mbar) {
    asm volatile(
        "cp.async.bulk.tensor.2d.shared::cta.global.tile.mbarrier::complete_tx::bytes "
        "[%0], [%1, {%2, %3}], [%4];"
        :: "r"(dst), "l"(map), "r"(x), "r"(y), "r"(mbar) : "memory");
}

DEV_INLINE void ldsm_x4(uint32_t& r0, uint32_t& r1, uint32_t& r2, uint32_t& r3, uint32_t addr) {
    asm volatile("ldmatrix.sync.aligned.m8n8.x4.shared.b16 {%0, %1, %2, %3}, [%4];"
                 : "=r"(r0), "=r"(r1), "=r"(r2), "=r"(r3) : "r"(addr));
}

DEV_INLINE void mma_16816(float& d0, float& d1, float& d2, float& d3,
                          uint32_t a0, uint32_t a1, uint32_t a2, uint32_t a3,
                          uint32_t b0, uint32_t b1) {
    asm volatile(
        "mma.sync.aligned.m16n8k16.row.col.f32.f16.f16.f32 "
        "{%0, %1, %2, %3}, {%4, %5, %6, %7}, {%8, %9}, {%0, %1, %2, %3};"
        : "+f"(d0), "+f"(d1), "+f"(d2), "+f"(d3)
        : "r"(a0), "r"(a1), "r"(a2), "r"(a3), "r"(b0), "r"(b1));
}

// red.global.add.noftz.f16 — no return value (REDG, not ATOMG)
DEV_INLINE void red_add_f16(__half* addr, __half v) {
    unsigned short u = __half_as_ushort(v);
    asm volatile("red.global.add.noftz.f16 [%0], %1;" :: "l"(addr), "h"(u) : "memory");
}

// ============================================================================
// Fused prep: blocks [0, CONV_BLOCKS) convert W fp32->fp16;
//             blocks [CONV_BLOCKS, PREP_BLOCKS) scatter COO into g_A (REDG).
// A was zeroed by cudaMemsetAsync before this kernel.
// ============================================================================

__global__ void prep_fused_kernel(const float* __restrict__ w,
                                  const float* __restrict__ vals,
                                  const int* __restrict__ rows,
                                  const int* __restrict__ cols, int nnz) {
    if (blockIdx.x < CONV_BLOCKS) {
        size_t gstride = (size_t)CONV_BLOCKS * blockDim.x;
        size_t g = (size_t)blockIdx.x * blockDim.x + threadIdx.x;
        size_t nW = (size_t)NDIM * KDIM / 4;        // float4 groups
        const float4* src = reinterpret_cast<const float4*>(w);
        __half2* dst = reinterpret_cast<__half2*>(g_W);
        for (size_t i = g; i < nW; i += gstride) {
            float4 f = src[i];
            dst[2 * i]     = __floats2half2_rn(f.x, f.y);
            dst[2 * i + 1] = __floats2half2_rn(f.z, f.w);
        }
    } else {
        int nblk = PREP_BLOCKS - CONV_BLOCKS;
        int gstride = nblk * blockDim.x;
        int g = (blockIdx.x - CONV_BLOCKS) * blockDim.x + threadIdx.x;
        for (int i = g; i < nnz; i += gstride) {
            size_t idx = (size_t)__ldg(rows + i) * KDIM + __ldg(cols + i);
            red_add_f16(g_A + idx, __float2half_rn(__ldg(vals + i)));
        }
    }
}

// ============================================================================
// Persistent GEMM kernel (unchanged from R5)
// ============================================================================

struct FragA { uint32_t r[4][4]; };
struct FragB { uint32_t r[2][4]; };

__global__ void __launch_bounds__(NTHREADS, 1) gemm_f16_kernel(
    const __grid_constant__ CUtensorMap tmA,
    const __grid_constant__ CUtensorMap tmB,
    const float* __restrict__ bias,
    float* __restrict__ out)
{
    extern __shared__ char smem[];
    uint32_t sb = smem_u32(smem);
    int tid = threadIdx.x;
    int wid = tid >> 5;
    int lid = tid & 31;

    if (tid == 0) {
        for (int s = 0; s < STAGES; s++) {
            mbar_init(sb + OFF_FULL + s * 8, 1);
            mbar_init(sb + OFF_EMPTY + s * 8, 8);
        }
    }
    __syncthreads();

    if (wid == 8) {
        if (lid == 0) {
            int stage = 0, phase = 1;
            for (int t = blockIdx.x; t < NTILES; t += GRID) {
                int m0 = (t / NTILES_X) * BM;
                int n0 = (t % NTILES_X) * BN;
                for (int it = 0; it < KITERS; ++it) {
                    int k0 = it * BK;
                    mbar_wait_relaxed(sb + OFF_EMPTY + stage * 8, phase);
                    mbar_expect_tx(sb + OFF_FULL + stage * 8, STAGE_A + STAGE_B);
                    uint32_t aDst = sb + OFF_A + stage * STAGE_A;
                    uint32_t bDst = sb + OFF_B + stage * STAGE_B;
                    tma_load_2d(aDst,              &tmA, k0,      m0, sb + OFF_FULL + stage * 8);
                    tma_load_2d(aDst + HALF_BYTES, &tmA, k0 + 64, m0, sb + OFF_FULL + stage * 8);
                    tma_load_2d(bDst,              &tmB, k0,      n0, sb + OFF_FULL + stage * 8);
                    tma_load_2d(bDst + HALF_BYTES, &tmB, k0 + 64, n0, sb + OFF_FULL + stage * 8);
                    if (++stage == STAGES) { stage = 0; phase ^= 1; }
                }
            }
        }
        return;
    }

    int warp_m = wid >> 2;
    int warp_n = wid & 3;
    int wait_pos = warp_m ? 7 : 5;

    int a_row0 = warp_m * 64 + ((lid >> 3) & 1) * 8 + (lid & 7);
    int a_kh   = lid >> 4;
    int a_x7   = lid & 7;
    int b_row0 = warp_n * 32 + (lid >> 4) * 8 + (lid & 7);
    int b_kh   = (lid >> 3) & 1;
    int b_x7   = lid & 7;

    auto load_frags = [&](int stg, int s8, FragA& fa, FragB& fb) {
        int half = s8 >> 2;
        int s4   = s8 & 3;
        uint32_t aBase = sb + OFF_A + stg * STAGE_A + half * HALF_BYTES;
        uint32_t bBase = sb + OFF_B + stg * STAGE_B + half * HALF_BYTES;
        #pragma unroll
        for (int im = 0; im < 4; im++) {
            int row = a_row0 + im * 16;
            uint32_t addr = aBase + row * 128 + (((s4 * 2 + a_kh) ^ a_x7) << 4);
            ldsm_x4(fa.r[im][0], fa.r[im][1], fa.r[im][2], fa.r[im][3], addr);
        }
        #pragma unroll
        for (int jn = 0; jn < 2; jn++) {
            int row = b_row0 + jn * 16;
            uint32_t addr = bBase + row * 128 + (((s4 * 2 + b_kh) ^ b_x7) << 4);
            ldsm_x4(fb.r[jn][0], fb.r[jn][1], fb.r[jn][2], fb.r[jn][3], addr);
        }
    };

    FragA fa[2];
    FragB fb[2];
    int stage = 0, phase = 0;

    mbar_wait(sb + OFF_FULL, 0);
    load_frags(0, 0, fa[0], fb[0]);

    for (int t = blockIdx.x; t < NTILES; t += GRID) {
        int m0 = (t / NTILES_X) * BM;
        int n0 = (t % NTILES_X) * BN;
        bool last_tile = (t + GRID >= NTILES);

        float c[4][4][4];
        #pragma unroll
        for (int i = 0; i < 4; i++)
            #pragma unroll
            for (int j = 0; j < 4; j++)
                #pragma unroll
                for (int k = 0; k < 4; k++)
                    c[i][j][k] = 0.0f;

        for (int it = 0; it < KITERS; ++it) {
            bool has_next = !(last_tile && it == KITERS - 1);
            int ns = (stage + 1 == STAGES) ? 0 : stage + 1;
            int np = (stage + 1 == STAGES) ? (phase ^ 1) : phase;

            #pragma unroll
            for (int s8 = 0; s8 < 8; ++s8) {
                int cur = s8 & 1;
                int nxt = cur ^ 1;

                if (s8 == wait_pos && has_next)
                    mbar_wait(sb + OFF_FULL + ns * 8, np);

                if (s8 < 7) {
                    load_frags(stage, s8 + 1, fa[nxt], fb[nxt]);
                } else if (has_next) {
                    load_frags(ns, 0, fa[nxt], fb[nxt]);
                }

                #pragma unroll
                for (int im = 0; im < 4; im++)
                    #pragma unroll
                    for (int in_ = 0; in_ < 4; in_++) {
                        int j = in_ >> 1, p = (in_ & 1) * 2;
                        mma_16816(c[im][in_][0], c[im][in_][1], c[im][in_][2], c[im][in_][3],
                                  fa[cur].r[im][0], fa[cur].r[im][1],
                                  fa[cur].r[im][2], fa[cur].r[im][3],
                                  fb[cur].r[j][p], fb[cur].r[j][p + 1]);
                    }
            }
            if (lid == 0) mbar_arrive(sb + OFF_EMPTY + stage * 8);
            if (++stage == STAGES) { stage = 0; phase ^= 1; }
        }

        int col_base = n0 + warp_n * 32 + (lid & 3) * 2;
        int row_base = m0 + warp_m * 64 + (lid >> 2);
        #pragma unroll
        for (int in_ = 0; in_ < 4; in_++) {
            int col = col_base + in_ * 8;
            float2 b2 = *reinterpret_cast<const float2*>(bias + col);
            #pragma unroll
            for (int im = 0; im < 4; im++) {
                int r0 = row_base + im * 16;
                float2 v0 = make_float2(c[im][in_][0] + b2.x, c[im][in_][1] + b2.y);
                float2 v1 = make_float2(c[im][in_][2] + b2.x, c[im][in_][3] + b2.y);
                *reinterpret_cast<float2*>(out + (size_t)r0 * NDIM + col) = v0;
                *reinterpret_cast<float2*>(out + (size_t)(r0 + 8) * NDIM + col) = v1;
            }
        }
    }
}

// ============================================================================
// Host side
// ============================================================================

typedef CUresult (*PFN_encodeTiled_t)(
    CUtensorMap*, CUtensorMapDataType, cuuint32_t, void*,
    const cuuint64_t*, const cuuint64_t*, const cuuint32_t*, const cuuint32_t*,
    CUtensorMapInterleave, CUtensorMapSwizzle, CUtensorMapL2promotion,
    CUtensorMapFloatOOBfill);

extern "C" void kernel_launch(void* const* d_in, const int* in_sizes, int n_in,
                              void* d_out, int out_size) {
    const float* vals   = (const float*)d_in[0];
    const int*   rows   = (const int*)d_in[1];
    const int*   cols   = (const int*)d_in[2];
    const float* weight = (const float*)d_in[3];
    const float* bias   = (const float*)d_in[4];
    int nnz = in_sizes[0];

    void* pA = nullptr;
    void* pW = nullptr;
    cudaGetSymbolAddress(&pA, g_A);
    cudaGetSymbolAddress(&pW, g_W);

    PFN_encodeTiled_t encode = nullptr;
    cudaDriverEntryPointQueryResult qres;
    cudaGetDriverEntryPoint("cuTensorMapEncodeTiled", (void**)&encode,
                            cudaEnableDefault, &qres);

    CUtensorMap tmA, tmB;
    {
        cuuint64_t dims[2]    = {(cuuint64_t)KDIM, (cuuint64_t)MDIM};
        cuuint64_t strides[1] = {(cuuint64_t)KDIM * sizeof(__half)};
        cuuint32_t box[2]     = {64, (cuuint32_t)BM};
        cuuint32_t es[2]      = {1, 1};
        encode(&tmA, CU_TENSOR_MAP_DATA_TYPE_FLOAT16, 2, pA, dims, strides, box, es,
               CU_TENSOR_MAP_INTERLEAVE_NONE, CU_TENSOR_MAP_SWIZZLE_128B,
               CU_TENSOR_MAP_L2_PROMOTION_L2_128B, CU_TENSOR_MAP_FLOAT_OOB_FILL_NONE);
    }
    {
        cuuint64_t dims[2]    = {(cuuint64_t)KDIM, (cuuint64_t)NDIM};
        cuuint64_t strides[1] = {(cuuint64_t)KDIM * sizeof(__half)};
        cuuint32_t box[2]     = {64, (cuuint32_t)BN};
        cuuint32_t es[2]      = {1, 1};
        encode(&tmB, CU_TENSOR_MAP_DATA_TYPE_FLOAT16, 2, pW, dims, strides, box, es,
               CU_TENSOR_MAP_INTERLEAVE_NONE, CU_TENSOR_MAP_SWIZZLE_128B,
               CU_TENSOR_MAP_L2_PROMOTION_L2_128B, CU_TENSOR_MAP_FLOAT_OOB_FILL_NONE);
    }

    // zero A via driver memset (near-peak write BW, graph-capturable)
    cudaMemsetAsync(pA, 0, (size_t)MDIM * KDIM * sizeof(__half));

    // fused: W convert (blocks 0..703) || COO scatter with REDG (blocks 704..1183)
    prep_fused_kernel<<<PREP_BLOCKS, 256>>>(weight, vals, rows, cols, nnz);

    cudaFuncSetAttribute(gemm_f16_kernel,
                         cudaFuncAttributeMaxDynamicSharedMemorySize, SMEM_TOTAL);
    gemm_f16_kernel<<<GRID, NTHREADS, SMEM_TOTAL>>>(tmA, tmB, bias, (float*)d_out);
}